// round 10
// baseline (speedup 1.0000x reference)
#include <cuda_runtime.h>
#include <cuda_bf16.h>
#include <cstdint>

#define TT 512
#define BB 128
#define HH 512
#define G4 2048

typedef unsigned long long ull;

__device__ float g_xg[(size_t)TT * G4 * BB];   // [t][g][b]
__device__ float g_hs[(size_t)TT * BB * HH];   // [t][b][h]
__device__ float g_r[(size_t)BB * HH];
__device__ float g_e[(size_t)TT * BB];
__device__ unsigned g_flags[128 * 32];         // one padded slot per CTA

__device__ __forceinline__ ull fma2(ull a, ull b, ull c) {
    ull d; asm("fma.rn.f32x2 %0, %1, %2, %3;" : "=l"(d) : "l"(a), "l"(b), "l"(c)); return d;
}
__device__ __forceinline__ ull pack2(float x, float y) {
    ull r; asm("mov.b64 %0, {%1, %2};" : "=l"(r) : "f"(x), "f"(y)); return r;
}
__device__ __forceinline__ float2 unpack2(ull v) {
    float2 f; asm("mov.b64 {%0, %1}, %2;" : "=f"(f.x), "=f"(f.y) : "l"(v)); return f;
}

__global__ void k_init(float* e) {
    int i = blockIdx.x * 256 + threadIdx.x;
    if (i < TT * BB) e[i] = 0.f;
    if (i < 128 * 32) g_flags[i] = 0u;
}

// ---- xg[t][g][b] = x[b][t][:] @ W_ih[g][:] + bias[g].  tile: one t, 128 b x 128 g ----
__global__ __launch_bounds__(256, 2) void k_xg(
    const float* __restrict__ x, const float* __restrict__ Wih,
    const float* __restrict__ bih, const float* __restrict__ bhh,
    float* __restrict__ xg)
{
    __shared__ float As[2][8][132];
    __shared__ float Bs[2][8][132];
    extern __shared__ float slab[];   // 128*129
    const int tid = threadIdx.x;
    const int tx = tid & 15, ty = tid >> 4;
    const int tBlk = blockIdx.y, nBase = blockIdx.x * 128;
    const int lr = tid >> 1, lk = (tid & 1) * 4;
    const float* aptr = x + ((size_t)lr * TT + tBlk) * HH + lk;       // b = lr
    const float* bptr = Wih + (size_t)(nBase + lr) * HH + lk;

    ull acc[8][4];
#pragma unroll
    for (int i = 0; i < 8; i++)
#pragma unroll
        for (int j = 0; j < 4; j++) acc[i][j] = 0ull;

    {
        float4 av = *(const float4*)aptr;
        float4 bv = *(const float4*)bptr;
        As[0][lk+0][lr]=av.x; As[0][lk+1][lr]=av.y; As[0][lk+2][lr]=av.z; As[0][lk+3][lr]=av.w;
        Bs[0][lk+0][lr]=bv.x; Bs[0][lk+1][lr]=bv.y; Bs[0][lk+2][lr]=bv.z; Bs[0][lk+3][lr]=bv.w;
    }
    __syncthreads();
    int buf = 0;

    for (int k0 = 0; k0 < HH; k0 += 8) {
        const bool more = (k0 + 8) < HH;
        float4 av2, bv2;
        if (more) {
            av2 = *(const float4*)(aptr + k0 + 8);
            bv2 = *(const float4*)(bptr + k0 + 8);
        }
#pragma unroll
        for (int k = 0; k < 8; k++) {
            float4 a0 = *(const float4*)&As[buf][k][ty * 8];
            float4 a1 = *(const float4*)&As[buf][k][ty * 8 + 4];
            ulonglong2 b0 = *(const ulonglong2*)&Bs[buf][k][tx * 8];
            ulonglong2 b1 = *(const ulonglong2*)&Bs[buf][k][tx * 8 + 4];
            float af[8] = {a0.x, a0.y, a0.z, a0.w, a1.x, a1.y, a1.z, a1.w};
            ull bp[4] = {b0.x, b0.y, b1.x, b1.y};
#pragma unroll
            for (int i = 0; i < 8; i++) {
                ull ap = pack2(af[i], af[i]);
#pragma unroll
                for (int j = 0; j < 4; j++) acc[i][j] = fma2(ap, bp[j], acc[i][j]);
            }
        }
        if (more) {
            int nb = buf ^ 1;
            As[nb][lk+0][lr]=av2.x; As[nb][lk+1][lr]=av2.y; As[nb][lk+2][lr]=av2.z; As[nb][lk+3][lr]=av2.w;
            Bs[nb][lk+0][lr]=bv2.x; Bs[nb][lk+1][lr]=bv2.y; Bs[nb][lk+2][lr]=bv2.z; Bs[nb][lk+3][lr]=bv2.w;
        }
        __syncthreads();
        buf ^= 1;
    }

    // transpose epilogue -> slab[g_local][b]
    const int gc = nBase + tx * 8;
    float bias[8];
#pragma unroll
    for (int j = 0; j < 8; j++) bias[j] = bih[gc + j] + bhh[gc + j];
#pragma unroll
    for (int i = 0; i < 8; i++) {
        const int br = ty * 8 + i;
        float2 v0 = unpack2(acc[i][0]), v1 = unpack2(acc[i][1]);
        float2 v2 = unpack2(acc[i][2]), v3 = unpack2(acc[i][3]);
        slab[(tx*8+0)*129 + br] = v0.x + bias[0];
        slab[(tx*8+1)*129 + br] = v0.y + bias[1];
        slab[(tx*8+2)*129 + br] = v1.x + bias[2];
        slab[(tx*8+3)*129 + br] = v1.y + bias[3];
        slab[(tx*8+4)*129 + br] = v2.x + bias[4];
        slab[(tx*8+5)*129 + br] = v2.y + bias[5];
        slab[(tx*8+6)*129 + br] = v3.x + bias[6];
        slab[(tx*8+7)*129 + br] = v3.y + bias[7];
    }
    __syncthreads();
    float* obase = xg + ((size_t)tBlk * G4 + nBase) * BB;
    for (int i = tid; i < 128 * 32; i += 256) {
        int g = i >> 5, c4 = (i & 31) << 2;
        float4 v = make_float4(slab[g*129+c4], slab[g*129+c4+1], slab[g*129+c4+2], slab[g*129+c4+3]);
        *(float4*)(obase + (size_t)g * BB + c4) = v;
    }
}

// ---- persistent LSTM recurrence: 128 CTAs x 512 threads ----
// CTA bx owns h-cols [bx*4, bx*4+4); thread = (b = tid>>2, j = tid&3).
// w_s stride 516 floats: the 4 rows a warp reads land on distinct banks.
__global__ __launch_bounds__(512, 1) void k_lstm(
    const float* __restrict__ Whh, const float* __restrict__ xg,
    float* __restrict__ hs)
{
    extern __shared__ float sm[];
    float (*w_s)[516] = (float(*)[516])sm;       // 16 x 516 (33 KB)
    float* hb0 = sm + 16 * 516;                  // 128 x 132
    float* hb1 = hb0 + 128 * 132;

    const int tid = threadIdx.x;
    const int bx = blockIdx.x;
    const int b = tid >> 2;
    const int j = tid & 3;
    const int col = bx * 4 + j;
    const int q4 = j;                             // row index j within q = g*4 + j

    // weights: w_s[g*4+jj][k] = Whh[(g*512 + bx*4 + jj)*512 + k]
    for (int i = tid; i < 16 * 512; i += 512) {
        int q = i >> 9, k = i & 511;
        int g = q >> 2, jj = q & 3;
        w_s[q][k] = Whh[(size_t)(g * HH + bx * 4 + jj) * HH + k];
    }
    float c = 0.f;
    float xv[4];
#pragma unroll
    for (int g = 0; g < 4; g++)
        xv[g] = __ldcg(xg + (size_t)(g * HH + col) * BB + b);
    __syncthreads();

    for (int t = 0; t < TT; t++) {
        ull acc[4] = {0ull, 0ull, 0ull, 0ull};

        if (t > 0) {
            const float* hsrc = hs + (size_t)(t - 1) * BB * HH;
            for (int i = tid; i < 4096; i += 512) {
                int bl = i >> 5, k4 = (i & 31) << 2;
                *(float4*)&hb0[bl * 132 + k4] = __ldcg((const float4*)(hsrc + (size_t)bl * HH + k4));
            }
            __syncthreads();
            int buf = 0;
#pragma unroll
            for (int cch = 0; cch < 4; cch++) {
                if (cch < 3) {
                    float* dst = buf ? hb0 : hb1;
                    for (int i = tid; i < 4096; i += 512) {
                        int bl = i >> 5, k4 = (i & 31) << 2;
                        *(float4*)&dst[bl * 132 + k4] =
                            __ldcg((const float4*)(hsrc + (size_t)bl * HH + (cch + 1) * 128 + k4));
                    }
                }
                const float* hbr = buf ? hb1 : hb0;
                const int kb = cch * 128;
#pragma unroll 8
                for (int k = 0; k < 128; k += 4) {
                    ulonglong2 hv = *(const ulonglong2*)&hbr[b * 132 + k];
#pragma unroll
                    for (int g = 0; g < 4; g++) {
                        ulonglong2 wv = *(const ulonglong2*)&w_s[g * 4 + q4][kb + k];
                        acc[g] = fma2(wv.x, hv.x, acc[g]);
                        acc[g] = fma2(wv.y, hv.y, acc[g]);
                    }
                }
                __syncthreads();
                buf ^= 1;
            }
        }

        float2 p;
        p = unpack2(acc[0]); float gi = p.x + p.y + xv[0];
        p = unpack2(acc[1]); float gf = p.x + p.y + xv[1];
        p = unpack2(acc[2]); float gg = p.x + p.y + xv[2];
        p = unpack2(acc[3]); float go = p.x + p.y + xv[3];
        float si = 1.f / (1.f + expf(-gi));
        float sf = 1.f / (1.f + expf(-gf));
        float so = 1.f / (1.f + expf(-go));
        c = sf * c + si * tanhf(gg);
        float h = so * tanhf(c);
        __stcg(hs + ((size_t)t * BB + b) * HH + col, h);

        // prefetch next step's gate pre-activations (no dependency) to hide barrier
        if (t + 1 < TT) {
            const float* xn = xg + (size_t)(t + 1) * G4 * BB;
#pragma unroll
            for (int g = 0; g < 4; g++)
                xv[g] = __ldcg(xn + (size_t)(g * HH + col) * BB + b);
        }

        __threadfence();
        __syncthreads();
        if (tid == 0)
            *((volatile unsigned*)&g_flags[bx * 32]) = (unsigned)(t + 1);
        if (tid < 128) {
            volatile unsigned* fp = &g_flags[tid * 32];
            while (*fp < (unsigned)(t + 1)) { }
        }
        __threadfence();
        __syncthreads();
    }
}

// ---- r[b][g] = h_last[b][:] @ U1[g][512:1024] ----
__global__ __launch_bounds__(256) void k_r(
    const float* __restrict__ hs, const float* __restrict__ U1, float* __restrict__ r)
{
    __shared__ float hl[512];
    const int b = blockIdx.x, tid = threadIdx.x;
    for (int i = tid; i < 512; i += 256)
        hl[i] = hs[((size_t)(TT - 1) * BB + b) * HH + i];
    __syncthreads();
    for (int g = tid; g < 512; g += 256) {
        const float* up = U1 + (size_t)g * 1024 + 512;
        float acc = 0.f;
        for (int k = 0; k < 512; k += 4) {
            float4 u = *(const float4*)(up + k);
            acc += hl[k] * u.x + hl[k+1] * u.y + hl[k+2] * u.z + hl[k+3] * u.w;
        }
        r[(size_t)b * HH + g] = acc;
    }
}

// ---- e[m] += sum_g tanh(hs@U1a + x@U2 + r) * Ve[g] ----
__global__ __launch_bounds__(256, 2) void k_e(
    const float* __restrict__ hs, const float* __restrict__ x,
    const float* __restrict__ U1, const float* __restrict__ U2,
    const float* __restrict__ r, const float* __restrict__ Ve,
    float* __restrict__ e)
{
    __shared__ float As[2][8][132];
    __shared__ float Bs[2][8][132];
    const int tid = threadIdx.x;
    const int tx = tid & 15, ty = tid >> 4;
    const int mBase = blockIdx.y * 128, nBase = blockIdx.x * 128;
    const int lr = tid >> 1, lk = (tid & 1) * 4;
    const int m = mBase + lr;
    const float* aptrs[2] = { hs + (size_t)m * HH + lk,
                              x + ((size_t)(m & 127) * TT + (m >> 7)) * HH + lk };
    const float* bptrs[2] = { U1 + (size_t)(nBase + lr) * 1024 + lk,
                              U2 + (size_t)(nBase + lr) * 512 + lk };

    ull acc[8][4];
#pragma unroll
    for (int i = 0; i < 8; i++)
#pragma unroll
        for (int j = 0; j < 4; j++) acc[i][j] = 0ull;

    {
        float4 av = *(const float4*)aptrs[0];
        float4 bv = *(const float4*)bptrs[0];
        As[0][lk+0][lr]=av.x; As[0][lk+1][lr]=av.y; As[0][lk+2][lr]=av.z; As[0][lk+3][lr]=av.w;
        Bs[0][lk+0][lr]=bv.x; Bs[0][lk+1][lr]=bv.y; Bs[0][lk+2][lr]=bv.z; Bs[0][lk+3][lr]=bv.w;
    }
    __syncthreads();
    int buf = 0;

    for (int ph = 0; ph < 2; ph++) {
        const float* ap = aptrs[ph];
        const float* bp_ = bptrs[ph];
        for (int k0 = 0; k0 < HH; k0 += 8) {
            const bool last = (ph == 1) && (k0 + 8 >= HH);
            float4 av2, bv2;
            if (!last) {
                const float* an = (k0 + 8 < HH) ? ap + k0 + 8 : aptrs[1];
                const float* bn = (k0 + 8 < HH) ? bp_ + k0 + 8 : bptrs[1];
                av2 = *(const float4*)an;
                bv2 = *(const float4*)bn;
            }
#pragma unroll
            for (int k = 0; k < 8; k++) {
                float4 a0 = *(const float4*)&As[buf][k][ty * 8];
                float4 a1 = *(const float4*)&As[buf][k][ty * 8 + 4];
                ulonglong2 b0 = *(const ulonglong2*)&Bs[buf][k][tx * 8];
                ulonglong2 b1 = *(const ulonglong2*)&Bs[buf][k][tx * 8 + 4];
                float af[8] = {a0.x, a0.y, a0.z, a0.w, a1.x, a1.y, a1.z, a1.w};
                ull bp2[4] = {b0.x, b0.y, b1.x, b1.y};
#pragma unroll
                for (int i = 0; i < 8; i++) {
                    ull apk = pack2(af[i], af[i]);
#pragma unroll
                    for (int j = 0; j < 4; j++) acc[i][j] = fma2(apk, bp2[j], acc[i][j]);
                }
            }
            if (!last) {
                int nb = buf ^ 1;
                As[nb][lk+0][lr]=av2.x; As[nb][lk+1][lr]=av2.y; As[nb][lk+2][lr]=av2.z; As[nb][lk+3][lr]=av2.w;
                Bs[nb][lk+0][lr]=bv2.x; Bs[nb][lk+1][lr]=bv2.y; Bs[nb][lk+2][lr]=bv2.z; Bs[nb][lk+3][lr]=bv2.w;
            }
            __syncthreads();
            buf ^= 1;
        }
    }

    const int gc = nBase + tx * 8;
    float ve[8];
#pragma unroll
    for (int j = 0; j < 8; j++) ve[j] = Ve[gc + j];
#pragma unroll
    for (int i = 0; i < 8; i++) {
        const int brow = ty * 8 + i;
        const float* rr = r + (size_t)brow * HH + gc;
        float si = 0.f; float2 v;
        v = unpack2(acc[i][0]); si += tanhf(v.x + rr[0]) * ve[0] + tanhf(v.y + rr[1]) * ve[1];
        v = unpack2(acc[i][1]); si += tanhf(v.x + rr[2]) * ve[2] + tanhf(v.y + rr[3]) * ve[3];
        v = unpack2(acc[i][2]); si += tanhf(v.x + rr[4]) * ve[4] + tanhf(v.y + rr[5]) * ve[5];
        v = unpack2(acc[i][3]); si += tanhf(v.x + rr[6]) * ve[6] + tanhf(v.y + rr[7]) * ve[7];
#pragma unroll
        for (int o = 8; o >= 1; o >>= 1)
            si += __shfl_xor_sync(0xffffffffu, si, o, 16);
        if (tx == 0) atomicAdd(&e[mBase + ty * 8 + i], si);
    }
}

// ---- softmax over t, context, output head; one CTA per batch element ----
__global__ __launch_bounds__(256) void k_final(
    const float* __restrict__ hs, const float* __restrict__ e,
    const float* __restrict__ Wout, const float* __restrict__ bout,
    float* __restrict__ out)
{
    __shared__ float al[512];
    __shared__ float red[256];
    const int b = blockIdx.x, tid = threadIdx.x;

    float ev0 = e[(size_t)tid * BB + b];
    float ev1 = e[(size_t)(tid + 256) * BB + b];

    red[tid] = fmaxf(ev0, ev1);
    __syncthreads();
    for (int s = 128; s > 0; s >>= 1) {
        if (tid < s) red[tid] = fmaxf(red[tid], red[tid + s]);
        __syncthreads();
    }
    float mx = red[0];
    __syncthreads();
    float x0 = expf(ev0 - mx), x1 = expf(ev1 - mx);
    red[tid] = x0 + x1;
    __syncthreads();
    for (int s = 128; s > 0; s >>= 1) {
        if (tid < s) red[tid] += red[tid + s];
        __syncthreads();
    }
    float inv = 1.f / red[0];
    al[tid] = x0 * inv;
    al[tid + 256] = x1 * inv;
    __syncthreads();

    float ctx0 = 0.f, ctx1 = 0.f;
    for (int t = 0; t < TT; t++) {
        float a = al[t];
        const float* hp = hs + ((size_t)t * BB + b) * HH;
        ctx0 += a * hp[tid];
        ctx1 += a * hp[tid + 256];
    }

    float p0 = ctx0 * Wout[tid] + ctx1 * Wout[tid + 256];
    float p1 = ctx0 * Wout[512 + tid] + ctx1 * Wout[512 + tid + 256];
    red[tid] = p0;
    __syncthreads();
    for (int s = 128; s > 0; s >>= 1) {
        if (tid < s) red[tid] += red[tid + s];
        __syncthreads();
    }
    float mu = red[0] + bout[0];
    __syncthreads();
    red[tid] = p1;
    __syncthreads();
    for (int s = 128; s > 0; s >>= 1) {
        if (tid < s) red[tid] += red[tid + s];
        __syncthreads();
    }
    if (tid == 0) {
        float pv = red[0] + bout[1];
        float sp = (pv > 20.f) ? pv : log1pf(expf(pv));
        out[b] = mu;
        out[BB + b] = sp + 1e-5f;
    }
}

extern "C" void kernel_launch(void* const* d_in, const int* in_sizes, int n_in,
                              void* d_out, int out_size) {
    const float* x    = (const float*)d_in[0];
    const float* Wih  = (const float*)d_in[1];
    const float* Whh  = (const float*)d_in[2];
    const float* bih  = (const float*)d_in[3];
    const float* bhh  = (const float*)d_in[4];
    const float* Ve   = (const float*)d_in[5];
    const float* U1   = (const float*)d_in[6];
    const float* U2   = (const float*)d_in[7];
    const float* Wout = (const float*)d_in[8];
    const float* bout = (const float*)d_in[9];
    float* out = (float*)d_out;

    float *xg, *hs, *r, *e;
    cudaGetSymbolAddress((void**)&xg, g_xg);
    cudaGetSymbolAddress((void**)&hs, g_hs);
    cudaGetSymbolAddress((void**)&r,  g_r);
    cudaGetSymbolAddress((void**)&e,  g_e);

    const int lstm_smem = (16 * 516 + 2 * 128 * 132) * 4;
    cudaFuncSetAttribute(k_xg,   cudaFuncAttributeMaxDynamicSharedMemorySize, 128 * 129 * 4);
    cudaFuncSetAttribute(k_lstm, cudaFuncAttributeMaxDynamicSharedMemorySize, lstm_smem);

    k_init<<<(TT * BB + 255) / 256, 256>>>(e);
    {
        dim3 g(G4 / 128, TT);
        k_xg<<<g, 256, 128 * 129 * 4>>>(x, Wih, bih, bhh, xg);
    }
    k_lstm<<<128, 512, lstm_smem>>>(Whh, xg, hs);
    k_r<<<BB, 256>>>(hs, U1, r);
    {
        dim3 g(HH / 128, (TT * BB) / 128);
        k_e<<<g, 256>>>(hs, x, U1, U2, r, Ve, e);
    }
    k_final<<<BB, 256>>>(hs, e, Wout, bout, out);
}

// round 11
// speedup vs baseline: 1.4461x; 1.4461x over previous
#include <cuda_runtime.h>
#include <cuda_bf16.h>
#include <cstdint>

#define TT 512
#define BB 128
#define HH 512
#define G4 2048

typedef unsigned long long ull;

__device__ float g_xg[(size_t)TT * G4 * BB];   // [t][g][b]
__device__ float g_hs[(size_t)TT * BB * HH];   // [t][b][h]
__device__ float g_r[(size_t)BB * HH];
__device__ float g_e[(size_t)TT * BB];
__device__ unsigned g_flags[128 * 32];         // one padded slot per CTA

__device__ __forceinline__ ull fma2(ull a, ull b, ull c) {
    ull d; asm("fma.rn.f32x2 %0, %1, %2, %3;" : "=l"(d) : "l"(a), "l"(b), "l"(c)); return d;
}
__device__ __forceinline__ ull addf32x2(ull a, ull b) {
    ull d; asm("add.rn.f32x2 %0, %1, %2;" : "=l"(d) : "l"(a), "l"(b)); return d;
}
__device__ __forceinline__ ull pack2(float x, float y) {
    ull r; asm("mov.b64 %0, {%1, %2};" : "=l"(r) : "f"(x), "f"(y)); return r;
}
__device__ __forceinline__ float2 unpack2(ull v) {
    float2 f; asm("mov.b64 {%0, %1}, %2;" : "=f"(f.x), "=f"(f.y) : "l"(v)); return f;
}

__global__ void k_init(float* e) {
    int i = blockIdx.x * 256 + threadIdx.x;
    if (i < TT * BB) e[i] = 0.f;
    if (i < 128 * 32) g_flags[i] = 0u;
}

// ---- xg[t][g][b] = x[b][t][:] @ W_ih[g][:] + bias[g].  tile: one t, 128 b x 128 g ----
__global__ __launch_bounds__(256, 2) void k_xg(
    const float* __restrict__ x, const float* __restrict__ Wih,
    const float* __restrict__ bih, const float* __restrict__ bhh,
    float* __restrict__ xg)
{
    __shared__ float As[2][8][132];
    __shared__ float Bs[2][8][132];
    extern __shared__ float slab[];   // 128*129
    const int tid = threadIdx.x;
    const int tx = tid & 15, ty = tid >> 4;
    const int tBlk = blockIdx.y, nBase = blockIdx.x * 128;
    const int lr = tid >> 1, lk = (tid & 1) * 4;
    const float* aptr = x + ((size_t)lr * TT + tBlk) * HH + lk;       // b = lr
    const float* bptr = Wih + (size_t)(nBase + lr) * HH + lk;

    ull acc[8][4];
#pragma unroll
    for (int i = 0; i < 8; i++)
#pragma unroll
        for (int j = 0; j < 4; j++) acc[i][j] = 0ull;

    {
        float4 av = *(const float4*)aptr;
        float4 bv = *(const float4*)bptr;
        As[0][lk+0][lr]=av.x; As[0][lk+1][lr]=av.y; As[0][lk+2][lr]=av.z; As[0][lk+3][lr]=av.w;
        Bs[0][lk+0][lr]=bv.x; Bs[0][lk+1][lr]=bv.y; Bs[0][lk+2][lr]=bv.z; Bs[0][lk+3][lr]=bv.w;
    }
    __syncthreads();
    int buf = 0;

    for (int k0 = 0; k0 < HH; k0 += 8) {
        const bool more = (k0 + 8) < HH;
        float4 av2, bv2;
        if (more) {
            av2 = *(const float4*)(aptr + k0 + 8);
            bv2 = *(const float4*)(bptr + k0 + 8);
        }
#pragma unroll
        for (int k = 0; k < 8; k++) {
            float4 a0 = *(const float4*)&As[buf][k][ty * 8];
            float4 a1 = *(const float4*)&As[buf][k][ty * 8 + 4];
            ulonglong2 b0 = *(const ulonglong2*)&Bs[buf][k][tx * 8];
            ulonglong2 b1 = *(const ulonglong2*)&Bs[buf][k][tx * 8 + 4];
            float af[8] = {a0.x, a0.y, a0.z, a0.w, a1.x, a1.y, a1.z, a1.w};
            ull bp[4] = {b0.x, b0.y, b1.x, b1.y};
#pragma unroll
            for (int i = 0; i < 8; i++) {
                ull ap = pack2(af[i], af[i]);
#pragma unroll
                for (int j = 0; j < 4; j++) acc[i][j] = fma2(ap, bp[j], acc[i][j]);
            }
        }
        if (more) {
            int nb = buf ^ 1;
            As[nb][lk+0][lr]=av2.x; As[nb][lk+1][lr]=av2.y; As[nb][lk+2][lr]=av2.z; As[nb][lk+3][lr]=av2.w;
            Bs[nb][lk+0][lr]=bv2.x; Bs[nb][lk+1][lr]=bv2.y; Bs[nb][lk+2][lr]=bv2.z; Bs[nb][lk+3][lr]=bv2.w;
        }
        __syncthreads();
        buf ^= 1;
    }

    // transpose epilogue -> slab[g_local][b]
    const int gc = nBase + tx * 8;
    float bias[8];
#pragma unroll
    for (int j = 0; j < 8; j++) bias[j] = bih[gc + j] + bhh[gc + j];
#pragma unroll
    for (int i = 0; i < 8; i++) {
        const int br = ty * 8 + i;
        float2 v0 = unpack2(acc[i][0]), v1 = unpack2(acc[i][1]);
        float2 v2 = unpack2(acc[i][2]), v3 = unpack2(acc[i][3]);
        slab[(tx*8+0)*129 + br] = v0.x + bias[0];
        slab[(tx*8+1)*129 + br] = v0.y + bias[1];
        slab[(tx*8+2)*129 + br] = v1.x + bias[2];
        slab[(tx*8+3)*129 + br] = v1.y + bias[3];
        slab[(tx*8+4)*129 + br] = v2.x + bias[4];
        slab[(tx*8+5)*129 + br] = v2.y + bias[5];
        slab[(tx*8+6)*129 + br] = v3.x + bias[6];
        slab[(tx*8+7)*129 + br] = v3.y + bias[7];
    }
    __syncthreads();
    float* obase = xg + ((size_t)tBlk * G4 + nBase) * BB;
    for (int i = tid; i < 128 * 32; i += 256) {
        int g = i >> 5, c4 = (i & 31) << 2;
        float4 v = make_float4(slab[g*129+c4], slab[g*129+c4+1], slab[g*129+c4+2], slab[g*129+c4+3]);
        *(float4*)(obase + (size_t)g * BB + c4) = v;
    }
}

// ---- persistent LSTM recurrence v2 ----
// 128 CTAs x 512 thr. CTA bx: cb = bx>>6 (batch half, 64 b), cc = bx&63 (8 cols).
// Warp wid: rg = wid&7 -> col = cc*8+rg; bg = wid>>3 -> batches [cb*64+bg*32, +32).
// W_hh tile (4 gates x 512 k for this col) lives in REGISTERS, k-sliced per lane:
// lane owns k in {4*lane + 128c + i}. Per batch: 1 LDS.128 per lane per 128-k
// quarter, 32 fma2, then 5-level f32x2 butterfly; lane==it keeps the gates.
__global__ __launch_bounds__(512, 1) void k_lstm(
    const float* __restrict__ Whh, const float* __restrict__ xg,
    float* __restrict__ hs)
{
    extern __shared__ float hb[];   // 64 x 516 floats
    const int tid = threadIdx.x;
    const int bx = blockIdx.x;
    const int cb = bx >> 6;
    const int cc = bx & 63;
    const int wid = tid >> 5;
    const int lane = tid & 31;
    const int rg = wid & 7;
    const int bg = wid >> 3;
    const int col = cc * 8 + rg;
    const int bmine = cb * 64 + bg * 32 + lane;   // batch whose state this lane owns

    // W_hh -> registers (one time). wlo/whi[g][c] = packed pairs of
    // Whh[g*512+col][4*lane+128c + {0,1}] / {2,3}
    ull wlo[4][4], whi[4][4];
#pragma unroll
    for (int g = 0; g < 4; g++) {
        const float* wp = Whh + (size_t)(g * HH + col) * HH + 4 * lane;
#pragma unroll
        for (int c = 0; c < 4; c++) {
            float4 wv = *(const float4*)(wp + 128 * c);
            wlo[g][c] = pack2(wv.x, wv.y);
            whi[g][c] = pack2(wv.z, wv.w);
        }
    }

    float cst = 0.f;
    float xv[4];
#pragma unroll
    for (int g = 0; g < 4; g++)
        xv[g] = __ldcg(xg + (size_t)(g * HH + col) * BB + bmine);

    for (int t = 0; t < TT; t++) {
        ull g01 = 0ull, g23 = 0ull;   // packed (i,f) and (g,o) recurrent sums

        if (t > 0) {
            // stage h(t-1) for our 64 batches (full k range)
            const float* hsrc = hs + ((size_t)(t - 1) * BB + cb * 64) * HH;
            for (int i = tid; i < 64 * 128; i += 512) {
                int bl = i >> 7, k4 = (i & 127) << 2;
                *(float4*)&hb[bl * 516 + k4] =
                    __ldcg((const float4*)(hsrc + (size_t)bl * HH + k4));
            }
            __syncthreads();

            for (int it = 0; it < 32; it++) {
                const float* hrow = hb + (bg * 32 + it) * 516 + 4 * lane;
                ull a0[4] = {0ull,0ull,0ull,0ull}, a1[4] = {0ull,0ull,0ull,0ull};
#pragma unroll
                for (int c = 0; c < 4; c++) {
                    ulonglong2 hv = *(const ulonglong2*)(hrow + 128 * c);
#pragma unroll
                    for (int g = 0; g < 4; g++) {
                        a0[g] = fma2(wlo[g][c], hv.x, a0[g]);
                        a1[g] = fma2(whi[g][c], hv.y, a1[g]);
                    }
                }
                float s[4];
#pragma unroll
                for (int g = 0; g < 4; g++) {
                    float2 p = unpack2(addf32x2(a0[g], a1[g]));
                    s[g] = p.x + p.y;
                }
                ull p01 = pack2(s[0], s[1]);
                ull p23 = pack2(s[2], s[3]);
#pragma unroll
                for (int off = 16; off >= 1; off >>= 1) {
                    p01 = addf32x2(p01, __shfl_xor_sync(0xffffffffu, p01, off));
                    p23 = addf32x2(p23, __shfl_xor_sync(0xffffffffu, p23, off));
                }
                if (lane == it) { g01 = p01; g23 = p23; }
            }
        }

        float2 q0 = unpack2(g01), q1 = unpack2(g23);
        float gi = q0.x + xv[0];
        float gf = q0.y + xv[1];
        float gg = q1.x + xv[2];
        float go = q1.y + xv[3];
        float si = 1.f / (1.f + expf(-gi));
        float sf = 1.f / (1.f + expf(-gf));
        float so = 1.f / (1.f + expf(-go));
        cst = sf * cst + si * tanhf(gg);
        float h = so * tanhf(cst);
        __stcg(hs + ((size_t)t * BB + bmine) * HH + col, h);

        // prefetch next step's xg (independent of the recurrence)
        if (t + 1 < TT) {
            const float* xn = xg + (size_t)(t + 1) * G4 * BB;
#pragma unroll
            for (int g = 0; g < 4; g++)
                xv[g] = __ldcg(xn + (size_t)(g * HH + col) * BB + bmine);
        }

        // flag-array grid barrier (all 128 CTAs resident)
        __threadfence();
        __syncthreads();
        if (tid == 0)
            *((volatile unsigned*)&g_flags[bx * 32]) = (unsigned)(t + 1);
        if (tid < 128) {
            volatile unsigned* fp = &g_flags[tid * 32];
            while (*fp < (unsigned)(t + 1)) { }
        }
        __threadfence();
        __syncthreads();
    }
}

// ---- r[b][g] = h_last[b][:] @ U1[g][512:1024] ----
__global__ __launch_bounds__(256) void k_r(
    const float* __restrict__ hs, const float* __restrict__ U1, float* __restrict__ r)
{
    __shared__ float hl[512];
    const int b = blockIdx.x, tid = threadIdx.x;
    for (int i = tid; i < 512; i += 256)
        hl[i] = hs[((size_t)(TT - 1) * BB + b) * HH + i];
    __syncthreads();
    for (int g = tid; g < 512; g += 256) {
        const float* up = U1 + (size_t)g * 1024 + 512;
        float acc = 0.f;
        for (int k = 0; k < 512; k += 4) {
            float4 u = *(const float4*)(up + k);
            acc += hl[k] * u.x + hl[k+1] * u.y + hl[k+2] * u.z + hl[k+3] * u.w;
        }
        r[(size_t)b * HH + g] = acc;
    }
}

// ---- e[m] += sum_g tanh(hs@U1a + x@U2 + r) * Ve[g] ----
__global__ __launch_bounds__(256, 2) void k_e(
    const float* __restrict__ hs, const float* __restrict__ x,
    const float* __restrict__ U1, const float* __restrict__ U2,
    const float* __restrict__ r, const float* __restrict__ Ve,
    float* __restrict__ e)
{
    __shared__ float As[2][8][132];
    __shared__ float Bs[2][8][132];
    const int tid = threadIdx.x;
    const int tx = tid & 15, ty = tid >> 4;
    const int mBase = blockIdx.y * 128, nBase = blockIdx.x * 128;
    const int lr = tid >> 1, lk = (tid & 1) * 4;
    const int m = mBase + lr;
    const float* aptrs[2] = { hs + (size_t)m * HH + lk,
                              x + ((size_t)(m & 127) * TT + (m >> 7)) * HH + lk };
    const float* bptrs[2] = { U1 + (size_t)(nBase + lr) * 1024 + lk,
                              U2 + (size_t)(nBase + lr) * 512 + lk };

    ull acc[8][4];
#pragma unroll
    for (int i = 0; i < 8; i++)
#pragma unroll
        for (int j = 0; j < 4; j++) acc[i][j] = 0ull;

    {
        float4 av = *(const float4*)aptrs[0];
        float4 bv = *(const float4*)bptrs[0];
        As[0][lk+0][lr]=av.x; As[0][lk+1][lr]=av.y; As[0][lk+2][lr]=av.z; As[0][lk+3][lr]=av.w;
        Bs[0][lk+0][lr]=bv.x; Bs[0][lk+1][lr]=bv.y; Bs[0][lk+2][lr]=bv.z; Bs[0][lk+3][lr]=bv.w;
    }
    __syncthreads();
    int buf = 0;

    for (int ph = 0; ph < 2; ph++) {
        const float* ap = aptrs[ph];
        const float* bp_ = bptrs[ph];
        for (int k0 = 0; k0 < HH; k0 += 8) {
            const bool last = (ph == 1) && (k0 + 8 >= HH);
            float4 av2, bv2;
            if (!last) {
                const float* an = (k0 + 8 < HH) ? ap + k0 + 8 : aptrs[1];
                const float* bn = (k0 + 8 < HH) ? bp_ + k0 + 8 : bptrs[1];
                av2 = *(const float4*)an;
                bv2 = *(const float4*)bn;
            }
#pragma unroll
            for (int k = 0; k < 8; k++) {
                float4 a0 = *(const float4*)&As[buf][k][ty * 8];
                float4 a1 = *(const float4*)&As[buf][k][ty * 8 + 4];
                ulonglong2 b0 = *(const ulonglong2*)&Bs[buf][k][tx * 8];
                ulonglong2 b1 = *(const ulonglong2*)&Bs[buf][k][tx * 8 + 4];
                float af[8] = {a0.x, a0.y, a0.z, a0.w, a1.x, a1.y, a1.z, a1.w};
                ull bp2[4] = {b0.x, b0.y, b1.x, b1.y};
#pragma unroll
                for (int i = 0; i < 8; i++) {
                    ull apk = pack2(af[i], af[i]);
#pragma unroll
                    for (int j = 0; j < 4; j++) acc[i][j] = fma2(apk, bp2[j], acc[i][j]);
                }
            }
            if (!last) {
                int nb = buf ^ 1;
                As[nb][lk+0][lr]=av2.x; As[nb][lk+1][lr]=av2.y; As[nb][lk+2][lr]=av2.z; As[nb][lk+3][lr]=av2.w;
                Bs[nb][lk+0][lr]=bv2.x; Bs[nb][lk+1][lr]=bv2.y; Bs[nb][lk+2][lr]=bv2.z; Bs[nb][lk+3][lr]=bv2.w;
            }
            __syncthreads();
            buf ^= 1;
        }
    }

    const int gc = nBase + tx * 8;
    float ve[8];
#pragma unroll
    for (int j = 0; j < 8; j++) ve[j] = Ve[gc + j];
#pragma unroll
    for (int i = 0; i < 8; i++) {
        const int brow = ty * 8 + i;
        const float* rr = r + (size_t)brow * HH + gc;
        float si = 0.f; float2 v;
        v = unpack2(acc[i][0]); si += tanhf(v.x + rr[0]) * ve[0] + tanhf(v.y + rr[1]) * ve[1];
        v = unpack2(acc[i][1]); si += tanhf(v.x + rr[2]) * ve[2] + tanhf(v.y + rr[3]) * ve[3];
        v = unpack2(acc[i][2]); si += tanhf(v.x + rr[4]) * ve[4] + tanhf(v.y + rr[5]) * ve[5];
        v = unpack2(acc[i][3]); si += tanhf(v.x + rr[6]) * ve[6] + tanhf(v.y + rr[7]) * ve[7];
#pragma unroll
        for (int o = 8; o >= 1; o >>= 1)
            si += __shfl_xor_sync(0xffffffffu, si, o, 16);
        if (tx == 0) atomicAdd(&e[mBase + ty * 8 + i], si);
    }
}

// ---- softmax over t, context, output head; one CTA per batch element ----
__global__ __launch_bounds__(256) void k_final(
    const float* __restrict__ hs, const float* __restrict__ e,
    const float* __restrict__ Wout, const float* __restrict__ bout,
    float* __restrict__ out)
{
    __shared__ float al[512];
    __shared__ float red[256];
    const int b = blockIdx.x, tid = threadIdx.x;

    float ev0 = e[(size_t)tid * BB + b];
    float ev1 = e[(size_t)(tid + 256) * BB + b];

    red[tid] = fmaxf(ev0, ev1);
    __syncthreads();
    for (int s = 128; s > 0; s >>= 1) {
        if (tid < s) red[tid] = fmaxf(red[tid], red[tid + s]);
        __syncthreads();
    }
    float mx = red[0];
    __syncthreads();
    float x0 = expf(ev0 - mx), x1 = expf(ev1 - mx);
    red[tid] = x0 + x1;
    __syncthreads();
    for (int s = 128; s > 0; s >>= 1) {
        if (tid < s) red[tid] += red[tid + s];
        __syncthreads();
    }
    float inv = 1.f / red[0];
    al[tid] = x0 * inv;
    al[tid + 256] = x1 * inv;
    __syncthreads();

    float ctx0 = 0.f, ctx1 = 0.f;
    for (int t = 0; t < TT; t++) {
        float a = al[t];
        const float* hp = hs + ((size_t)t * BB + b) * HH;
        ctx0 += a * hp[tid];
        ctx1 += a * hp[tid + 256];
    }

    float p0 = ctx0 * Wout[tid] + ctx1 * Wout[tid + 256];
    float p1 = ctx0 * Wout[512 + tid] + ctx1 * Wout[512 + tid + 256];
    red[tid] = p0;
    __syncthreads();
    for (int s = 128; s > 0; s >>= 1) {
        if (tid < s) red[tid] += red[tid + s];
        __syncthreads();
    }
    float mu = red[0] + bout[0];
    __syncthreads();
    red[tid] = p1;
    __syncthreads();
    for (int s = 128; s > 0; s >>= 1) {
        if (tid < s) red[tid] += red[tid + s];
        __syncthreads();
    }
    if (tid == 0) {
        float pv = red[0] + bout[1];
        float sp = (pv > 20.f) ? pv : log1pf(expf(pv));
        out[b] = mu;
        out[BB + b] = sp + 1e-5f;
    }
}

extern "C" void kernel_launch(void* const* d_in, const int* in_sizes, int n_in,
                              void* d_out, int out_size) {
    const float* x    = (const float*)d_in[0];
    const float* Wih  = (const float*)d_in[1];
    const float* Whh  = (const float*)d_in[2];
    const float* bih  = (const float*)d_in[3];
    const float* bhh  = (const float*)d_in[4];
    const float* Ve   = (const float*)d_in[5];
    const float* U1   = (const float*)d_in[6];
    const float* U2   = (const float*)d_in[7];
    const float* Wout = (const float*)d_in[8];
    const float* bout = (const float*)d_in[9];
    float* out = (float*)d_out;

    float *xg, *hs, *r, *e;
    cudaGetSymbolAddress((void**)&xg, g_xg);
    cudaGetSymbolAddress((void**)&hs, g_hs);
    cudaGetSymbolAddress((void**)&r,  g_r);
    cudaGetSymbolAddress((void**)&e,  g_e);

    const int lstm_smem = 64 * 516 * 4;   // 132096 B
    cudaFuncSetAttribute(k_xg,   cudaFuncAttributeMaxDynamicSharedMemorySize, 128 * 129 * 4);
    cudaFuncSetAttribute(k_lstm, cudaFuncAttributeMaxDynamicSharedMemorySize, lstm_smem);

    k_init<<<(TT * BB + 255) / 256, 256>>>(e);
    {
        dim3 g(G4 / 128, TT);
        k_xg<<<g, 256, 128 * 129 * 4>>>(x, Wih, bih, bhh, xg);
    }
    k_lstm<<<128, 512, lstm_smem>>>(Whh, xg, hs);
    k_r<<<BB, 256>>>(hs, U1, r);
    {
        dim3 g(HH / 128, (TT * BB) / 128);
        k_e<<<g, 256>>>(hs, x, U1, U2, r, Ve, e);
    }
    k_final<<<BB, 256>>>(hs, e, Wout, bout, out);
}

// round 13
// speedup vs baseline: 1.4695x; 1.0162x over previous
#include <cuda_runtime.h>
#include <cuda_bf16.h>
#include <cstdint>

#define TT 512
#define BB 128
#define HH 512
#define G4 2048

typedef unsigned long long ull;

__device__ float g_xg[(size_t)TT * G4 * BB];   // [t][g][b]
__device__ float g_hs[(size_t)TT * BB * HH];   // [t][b][h]
__device__ float g_r[(size_t)BB * HH];
__device__ float g_e[(size_t)TT * BB];
__device__ unsigned g_flags[128 * 32];         // one padded slot per CTA

__device__ __forceinline__ ull fma2(ull a, ull b, ull c) {
    ull d; asm("fma.rn.f32x2 %0, %1, %2, %3;" : "=l"(d) : "l"(a), "l"(b), "l"(c)); return d;
}
__device__ __forceinline__ ull addf32x2(ull a, ull b) {
    ull d; asm("add.rn.f32x2 %0, %1, %2;" : "=l"(d) : "l"(a), "l"(b)); return d;
}
__device__ __forceinline__ ull pack2(float x, float y) {
    ull r; asm("mov.b64 %0, {%1, %2};" : "=l"(r) : "f"(x), "f"(y)); return r;
}
__device__ __forceinline__ float2 unpack2(ull v) {
    float2 f; asm("mov.b64 {%0, %1}, %2;" : "=f"(f.x), "=f"(f.y) : "l"(v)); return f;
}

__global__ void k_init(float* e) {
    int i = blockIdx.x * 256 + threadIdx.x;
    if (i < TT * BB) e[i] = 0.f;
    if (i < 128 * 32) g_flags[i] = 0u;
}

// no-op spacer so ncu's fixed capture slot lands on k_lstm
__global__ void k_nop() {}

// ---- xg[t][g][b] = x[b][t][:] @ W_ih[g][:] + bias[g].  tile: one t, 128 b x 128 g ----
__global__ __launch_bounds__(256, 2) void k_xg(
    const float* __restrict__ x, const float* __restrict__ Wih,
    const float* __restrict__ bih, const float* __restrict__ bhh,
    float* __restrict__ xg)
{
    __shared__ float As[2][8][132];
    __shared__ float Bs[2][8][132];
    extern __shared__ float slab[];   // 128*129
    const int tid = threadIdx.x;
    const int tx = tid & 15, ty = tid >> 4;
    const int tBlk = blockIdx.y, nBase = blockIdx.x * 128;
    const int lr = tid >> 1, lk = (tid & 1) * 4;
    const float* aptr = x + ((size_t)lr * TT + tBlk) * HH + lk;       // b = lr
    const float* bptr = Wih + (size_t)(nBase + lr) * HH + lk;

    ull acc[8][4];
#pragma unroll
    for (int i = 0; i < 8; i++)
#pragma unroll
        for (int j = 0; j < 4; j++) acc[i][j] = 0ull;

    {
        float4 av = *(const float4*)aptr;
        float4 bv = *(const float4*)bptr;
        As[0][lk+0][lr]=av.x; As[0][lk+1][lr]=av.y; As[0][lk+2][lr]=av.z; As[0][lk+3][lr]=av.w;
        Bs[0][lk+0][lr]=bv.x; Bs[0][lk+1][lr]=bv.y; Bs[0][lk+2][lr]=bv.z; Bs[0][lk+3][lr]=bv.w;
    }
    __syncthreads();
    int buf = 0;

    for (int k0 = 0; k0 < HH; k0 += 8) {
        const bool more = (k0 + 8) < HH;
        float4 av2, bv2;
        if (more) {
            av2 = *(const float4*)(aptr + k0 + 8);
            bv2 = *(const float4*)(bptr + k0 + 8);
        }
#pragma unroll
        for (int k = 0; k < 8; k++) {
            float4 a0 = *(const float4*)&As[buf][k][ty * 8];
            float4 a1 = *(const float4*)&As[buf][k][ty * 8 + 4];
            ulonglong2 b0 = *(const ulonglong2*)&Bs[buf][k][tx * 8];
            ulonglong2 b1 = *(const ulonglong2*)&Bs[buf][k][tx * 8 + 4];
            float af[8] = {a0.x, a0.y, a0.z, a0.w, a1.x, a1.y, a1.z, a1.w};
            ull bp[4] = {b0.x, b0.y, b1.x, b1.y};
#pragma unroll
            for (int i = 0; i < 8; i++) {
                ull ap = pack2(af[i], af[i]);
#pragma unroll
                for (int j = 0; j < 4; j++) acc[i][j] = fma2(ap, bp[j], acc[i][j]);
            }
        }
        if (more) {
            int nb = buf ^ 1;
            As[nb][lk+0][lr]=av2.x; As[nb][lk+1][lr]=av2.y; As[nb][lk+2][lr]=av2.z; As[nb][lk+3][lr]=av2.w;
            Bs[nb][lk+0][lr]=bv2.x; Bs[nb][lk+1][lr]=bv2.y; Bs[nb][lk+2][lr]=bv2.z; Bs[nb][lk+3][lr]=bv2.w;
        }
        __syncthreads();
        buf ^= 1;
    }

    // transpose epilogue -> slab[g_local][b]
    const int gc = nBase + tx * 8;
    float bias[8];
#pragma unroll
    for (int j = 0; j < 8; j++) bias[j] = bih[gc + j] + bhh[gc + j];
#pragma unroll
    for (int i = 0; i < 8; i++) {
        const int br = ty * 8 + i;
        float2 v0 = unpack2(acc[i][0]), v1 = unpack2(acc[i][1]);
        float2 v2 = unpack2(acc[i][2]), v3 = unpack2(acc[i][3]);
        slab[(tx*8+0)*129 + br] = v0.x + bias[0];
        slab[(tx*8+1)*129 + br] = v0.y + bias[1];
        slab[(tx*8+2)*129 + br] = v1.x + bias[2];
        slab[(tx*8+3)*129 + br] = v1.y + bias[3];
        slab[(tx*8+4)*129 + br] = v2.x + bias[4];
        slab[(tx*8+5)*129 + br] = v2.y + bias[5];
        slab[(tx*8+6)*129 + br] = v3.x + bias[6];
        slab[(tx*8+7)*129 + br] = v3.y + bias[7];
    }
    __syncthreads();
    float* obase = xg + ((size_t)tBlk * G4 + nBase) * BB;
    for (int i = tid; i < 128 * 32; i += 256) {
        int g = i >> 5, c4 = (i & 31) << 2;
        float4 v = make_float4(slab[g*129+c4], slab[g*129+c4+1], slab[g*129+c4+2], slab[g*129+c4+3]);
        *(float4*)(obase + (size_t)g * BB + c4) = v;
    }
}

// ---- persistent LSTM recurrence v2 + fence-free release/acquire barrier ----
// 128 CTAs x 512 thr. CTA bx: cb = bx>>6 (batch half, 64 b), cc = bx&63 (8 cols).
// Warp wid: rg = wid&7 -> col = cc*8+rg; bg = wid>>3 -> batches [cb*64+bg*32, +32).
// W_hh tile (4 gates x 512 k for this col) lives in REGISTERS, k-sliced per lane.
__global__ __launch_bounds__(512, 1) void k_lstm(
    const float* __restrict__ Whh, const float* __restrict__ xg,
    float* __restrict__ hs)
{
    extern __shared__ float hb[];   // 64 x 516 floats
    const int tid = threadIdx.x;
    const int bx = blockIdx.x;
    const int cb = bx >> 6;
    const int cc = bx & 63;
    const int wid = tid >> 5;
    const int lane = tid & 31;
    const int rg = wid & 7;
    const int bg = wid >> 3;
    const int col = cc * 8 + rg;
    const int bmine = cb * 64 + bg * 32 + lane;   // batch whose state this lane owns

    // W_hh -> registers (one time)
    ull wlo[4][4], whi[4][4];
#pragma unroll
    for (int g = 0; g < 4; g++) {
        const float* wp = Whh + (size_t)(g * HH + col) * HH + 4 * lane;
#pragma unroll
        for (int c = 0; c < 4; c++) {
            float4 wv = *(const float4*)(wp + 128 * c);
            wlo[g][c] = pack2(wv.x, wv.y);
            whi[g][c] = pack2(wv.z, wv.w);
        }
    }

    float cst = 0.f;
    float xv[4];
#pragma unroll
    for (int g = 0; g < 4; g++)
        xv[g] = __ldcg(xg + (size_t)(g * HH + col) * BB + bmine);

    unsigned* myflag = &g_flags[bx * 32];
    unsigned* pollflag = &g_flags[(tid & 127) * 32];

    for (int t = 0; t < TT; t++) {
        ull g01 = 0ull, g23 = 0ull;   // packed (i,f) and (g,o) recurrent sums

        if (t > 0) {
            // stage h(t-1) for our 64 batches (full k range)
            const float* hsrc = hs + ((size_t)(t - 1) * BB + cb * 64) * HH;
            for (int i = tid; i < 64 * 128; i += 512) {
                int bl = i >> 7, k4 = (i & 127) << 2;
                *(float4*)&hb[bl * 516 + k4] =
                    __ldcg((const float4*)(hsrc + (size_t)bl * HH + k4));
            }
            __syncthreads();

            for (int it = 0; it < 32; it++) {
                const float* hrow = hb + (bg * 32 + it) * 516 + 4 * lane;
                ull a0[4] = {0ull,0ull,0ull,0ull}, a1[4] = {0ull,0ull,0ull,0ull};
#pragma unroll
                for (int c = 0; c < 4; c++) {
                    ulonglong2 hv = *(const ulonglong2*)(hrow + 128 * c);
#pragma unroll
                    for (int g = 0; g < 4; g++) {
                        a0[g] = fma2(wlo[g][c], hv.x, a0[g]);
                        a1[g] = fma2(whi[g][c], hv.y, a1[g]);
                    }
                }
                float s[4];
#pragma unroll
                for (int g = 0; g < 4; g++) {
                    float2 p = unpack2(addf32x2(a0[g], a1[g]));
                    s[g] = p.x + p.y;
                }
                ull p01 = pack2(s[0], s[1]);
                ull p23 = pack2(s[2], s[3]);
#pragma unroll
                for (int off = 16; off >= 1; off >>= 1) {
                    p01 = addf32x2(p01, __shfl_xor_sync(0xffffffffu, p01, off));
                    p23 = addf32x2(p23, __shfl_xor_sync(0xffffffffu, p23, off));
                }
                if (lane == it) { g01 = p01; g23 = p23; }
            }
        }

        float2 q0 = unpack2(g01), q1 = unpack2(g23);
        float gi = q0.x + xv[0];
        float gf = q0.y + xv[1];
        float gg = q1.x + xv[2];
        float go = q1.y + xv[3];
        float si = 1.f / (1.f + expf(-gi));
        float sf = 1.f / (1.f + expf(-gf));
        float so = 1.f / (1.f + expf(-go));
        cst = sf * cst + si * tanhf(gg);
        float h = so * tanhf(cst);
        __stcg(hs + ((size_t)t * BB + bmine) * HH + col, h);

        // prefetch next step's xg (independent of the recurrence)
        if (t + 1 < TT) {
            const float* xn = xg + (size_t)(t + 1) * G4 * BB;
#pragma unroll
            for (int g = 0; g < 4; g++)
                xv[g] = __ldcg(xn + (size_t)(g * HH + col) * BB + bmine);
        }

        // ---- fence-free release/acquire grid barrier ----
        // release: all threads' h-stores happen-before tid0's st.release via bar.sync
        __syncthreads();
        if (tid == 0) {
            asm volatile("st.release.gpu.u32 [%0], %1;"
                         :: "l"(myflag), "r"((unsigned)(t + 1)) : "memory");
        }
        // acquire: 128 pollers each watch one CTA's flag with ld.acquire
        if (tid < 128) {
            unsigned v;
            do {
                asm volatile("ld.acquire.gpu.u32 %0, [%1];"
                             : "=r"(v) : "l"(pollflag) : "memory");
            } while (v < (unsigned)(t + 1));
        }
        __syncthreads();
    }
}

// ---- r[b][g] = h_last[b][:] @ U1[g][512:1024] ----
__global__ __launch_bounds__(256) void k_r(
    const float* __restrict__ hs, const float* __restrict__ U1, float* __restrict__ r)
{
    __shared__ float hl[512];
    const int b = blockIdx.x, tid = threadIdx.x;
    for (int i = tid; i < 512; i += 256)
        hl[i] = hs[((size_t)(TT - 1) * BB + b) * HH + i];
    __syncthreads();
    for (int g = tid; g < 512; g += 256) {
        const float* up = U1 + (size_t)g * 1024 + 512;
        float acc = 0.f;
        for (int k = 0; k < 512; k += 4) {
            float4 u = *(const float4*)(up + k);
            acc += hl[k] * u.x + hl[k+1] * u.y + hl[k+2] * u.z + hl[k+3] * u.w;
        }
        r[(size_t)b * HH + g] = acc;
    }
}

// ---- e[m] += sum_g tanh(hs@U1a + x@U2 + r) * Ve[g] ----
__global__ __launch_bounds__(256, 2) void k_e(
    const float* __restrict__ hs, const float* __restrict__ x,
    const float* __restrict__ U1, const float* __restrict__ U2,
    const float* __restrict__ r, const float* __restrict__ Ve,
    float* __restrict__ e)
{
    __shared__ float As[2][8][132];
    __shared__ float Bs[2][8][132];
    const int tid = threadIdx.x;
    const int tx = tid & 15, ty = tid >> 4;
    const int mBase = blockIdx.y * 128, nBase = blockIdx.x * 128;
    const int lr = tid >> 1, lk = (tid & 1) * 4;
    const int m = mBase + lr;
    const float* aptrs[2] = { hs + (size_t)m * HH + lk,
                              x + ((size_t)(m & 127) * TT + (m >> 7)) * HH + lk };
    const float* bptrs[2] = { U1 + (size_t)(nBase + lr) * 1024 + lk,
                              U2 + (size_t)(nBase + lr) * 512 + lk };

    ull acc[8][4];
#pragma unroll
    for (int i = 0; i < 8; i++)
#pragma unroll
        for (int j = 0; j < 4; j++) acc[i][j] = 0ull;

    {
        float4 av = *(const float4*)aptrs[0];
        float4 bv = *(const float4*)bptrs[0];
        As[0][lk+0][lr]=av.x; As[0][lk+1][lr]=av.y; As[0][lk+2][lr]=av.z; As[0][lk+3][lr]=av.w;
        Bs[0][lk+0][lr]=bv.x; Bs[0][lk+1][lr]=bv.y; Bs[0][lk+2][lr]=bv.z; Bs[0][lk+3][lr]=bv.w;
    }
    __syncthreads();
    int buf = 0;

    for (int ph = 0; ph < 2; ph++) {
        const float* ap = aptrs[ph];
        const float* bp_ = bptrs[ph];
        for (int k0 = 0; k0 < HH; k0 += 8) {
            const bool last = (ph == 1) && (k0 + 8 >= HH);
            float4 av2, bv2;
            if (!last) {
                const float* an = (k0 + 8 < HH) ? ap + k0 + 8 : aptrs[1];
                const float* bn = (k0 + 8 < HH) ? bp_ + k0 + 8 : bptrs[1];
                av2 = *(const float4*)an;
                bv2 = *(const float4*)bn;
            }
#pragma unroll
            for (int k = 0; k < 8; k++) {
                float4 a0 = *(const float4*)&As[buf][k][ty * 8];
                float4 a1 = *(const float4*)&As[buf][k][ty * 8 + 4];
                ulonglong2 b0 = *(const ulonglong2*)&Bs[buf][k][tx * 8];
                ulonglong2 b1 = *(const ulonglong2*)&Bs[buf][k][tx * 8 + 4];
                float af[8] = {a0.x, a0.y, a0.z, a0.w, a1.x, a1.y, a1.z, a1.w};
                ull bp2[4] = {b0.x, b0.y, b1.x, b1.y};
#pragma unroll
                for (int i = 0; i < 8; i++) {
                    ull apk = pack2(af[i], af[i]);
#pragma unroll
                    for (int j = 0; j < 4; j++) acc[i][j] = fma2(apk, bp2[j], acc[i][j]);
                }
            }
            if (!last) {
                int nb = buf ^ 1;
                As[nb][lk+0][lr]=av2.x; As[nb][lk+1][lr]=av2.y; As[nb][lk+2][lr]=av2.z; As[nb][lk+3][lr]=av2.w;
                Bs[nb][lk+0][lr]=bv2.x; Bs[nb][lk+1][lr]=bv2.y; Bs[nb][lk+2][lr]=bv2.z; Bs[nb][lk+3][lr]=bv2.w;
            }
            __syncthreads();
            buf ^= 1;
        }
    }

    const int gc = nBase + tx * 8;
    float ve[8];
#pragma unroll
    for (int j = 0; j < 8; j++) ve[j] = Ve[gc + j];
#pragma unroll
    for (int i = 0; i < 8; i++) {
        const int brow = ty * 8 + i;
        const float* rr = r + (size_t)brow * HH + gc;
        float si = 0.f; float2 v;
        v = unpack2(acc[i][0]); si += tanhf(v.x + rr[0]) * ve[0] + tanhf(v.y + rr[1]) * ve[1];
        v = unpack2(acc[i][1]); si += tanhf(v.x + rr[2]) * ve[2] + tanhf(v.y + rr[3]) * ve[3];
        v = unpack2(acc[i][2]); si += tanhf(v.x + rr[4]) * ve[4] + tanhf(v.y + rr[5]) * ve[5];
        v = unpack2(acc[i][3]); si += tanhf(v.x + rr[6]) * ve[6] + tanhf(v.y + rr[7]) * ve[7];
#pragma unroll
        for (int o = 8; o >= 1; o >>= 1)
            si += __shfl_xor_sync(0xffffffffu, si, o, 16);
        if (tx == 0) atomicAdd(&e[mBase + ty * 8 + i], si);
    }
}

// ---- softmax over t, context, output head; one CTA per batch element ----
__global__ __launch_bounds__(256) void k_final(
    const float* __restrict__ hs, const float* __restrict__ e,
    const float* __restrict__ Wout, const float* __restrict__ bout,
    float* __restrict__ out)
{
    __shared__ float al[512];
    __shared__ float red[256];
    const int b = blockIdx.x, tid = threadIdx.x;

    float ev0 = e[(size_t)tid * BB + b];
    float ev1 = e[(size_t)(tid + 256) * BB + b];

    red[tid] = fmaxf(ev0, ev1);
    __syncthreads();
    for (int s = 128; s > 0; s >>= 1) {
        if (tid < s) red[tid] = fmaxf(red[tid], red[tid + s]);
        __syncthreads();
    }
    float mx = red[0];
    __syncthreads();
    float x0 = expf(ev0 - mx), x1 = expf(ev1 - mx);
    red[tid] = x0 + x1;
    __syncthreads();
    for (int s = 128; s > 0; s >>= 1) {
        if (tid < s) red[tid] += red[tid + s];
        __syncthreads();
    }
    float inv = 1.f / red[0];
    al[tid] = x0 * inv;
    al[tid + 256] = x1 * inv;
    __syncthreads();

    float ctx0 = 0.f, ctx1 = 0.f;
    for (int t = 0; t < TT; t++) {
        float a = al[t];
        const float* hp = hs + ((size_t)t * BB + b) * HH;
        ctx0 += a * hp[tid];
        ctx1 += a * hp[tid + 256];
    }

    float p0 = ctx0 * Wout[tid] + ctx1 * Wout[tid + 256];
    float p1 = ctx0 * Wout[512 + tid] + ctx1 * Wout[512 + tid + 256];
    red[tid] = p0;
    __syncthreads();
    for (int s = 128; s > 0; s >>= 1) {
        if (tid < s) red[tid] += red[tid + s];
        __syncthreads();
    }
    float mu = red[0] + bout[0];
    __syncthreads();
    red[tid] = p1;
    __syncthreads();
    for (int s = 128; s > 0; s >>= 1) {
        if (tid < s) red[tid] += red[tid + s];
        __syncthreads();
    }
    if (tid == 0) {
        float pv = red[0] + bout[1];
        float sp = (pv > 20.f) ? pv : log1pf(expf(pv));
        out[b] = mu;
        out[BB + b] = sp + 1e-5f;
    }
}

extern "C" void kernel_launch(void* const* d_in, const int* in_sizes, int n_in,
                              void* d_out, int out_size) {
    const float* x    = (const float*)d_in[0];
    const float* Wih  = (const float*)d_in[1];
    const float* Whh  = (const float*)d_in[2];
    const float* bih  = (const float*)d_in[3];
    const float* bhh  = (const float*)d_in[4];
    const float* Ve   = (const float*)d_in[5];
    const float* U1   = (const float*)d_in[6];
    const float* U2   = (const float*)d_in[7];
    const float* Wout = (const float*)d_in[8];
    const float* bout = (const float*)d_in[9];
    float* out = (float*)d_out;

    float *xg, *hs, *r, *e;
    cudaGetSymbolAddress((void**)&xg, g_xg);
    cudaGetSymbolAddress((void**)&hs, g_hs);
    cudaGetSymbolAddress((void**)&r,  g_r);
    cudaGetSymbolAddress((void**)&e,  g_e);

    const int lstm_smem = 64 * 516 * 4;   // 132096 B
    cudaFuncSetAttribute(k_xg,   cudaFuncAttributeMaxDynamicSharedMemorySize, 128 * 129 * 4);
    cudaFuncSetAttribute(k_lstm, cudaFuncAttributeMaxDynamicSharedMemorySize, lstm_smem);

    k_init<<<(TT * BB + 255) / 256, 256>>>(e);
    {
        dim3 g(G4 / 128, TT);
        k_xg<<<g, 256, 128 * 129 * 4>>>(x, Wih, bih, bhh, xg);
    }
    k_nop<<<1, 32>>>();   // spacer: shifts k_lstm into ncu's capture slot
    k_lstm<<<128, 512, lstm_smem>>>(Whh, xg, hs);
    k_r<<<BB, 256>>>(hs, U1, r);
    {
        dim3 g(HH / 128, (TT * BB) / 128);
        k_e<<<g, 256>>>(hs, x, U1, U2, r, Ve, e);
    }
    k_final<<<BB, 256>>>(hs, e, Wout, bout, out);
}